// round 7
// baseline (speedup 1.0000x reference)
#include <cuda_runtime.h>
#include <cstdint>

#define D 64
#define MAX_NODES 100000
#define MAX_EDGES 1600000
#define GR 64           // rows per GEMM block
#define SPAD 68         // sWt row stride (floats)
#define SNDS 66         // sNd row stride (u64)
#define SCAN_FLAG (1 << 30)

typedef unsigned long long u64;

__device__ float g_neigh[MAX_NODES * D];
__device__ int   g_idx64;
__device__ int   g_cnt[MAX_NODES];
__device__ int   g_start[MAX_NODES];
__device__ int   g_pos[MAX_NODES];
__device__ int   g_srcsorted[MAX_EDGES];
__device__ int   g_bsum[128];            // block aggregate | SCAN_FLAG

#define FMA_F32X2(d, a, b, c) \
    asm("fma.rn.f32x2 %0, %1, %2, %3;" : "=l"(d) : "l"(a), "l"(b), "l"(c))
#define DUP_F32X2(d, v) \
    asm("mov.b64 %0, {%1, %1};" : "=l"(d) : "f"(v))

// ---------------------------------------------------------------------------
// Fused: zero g_cnt + zero g_bsum + detect index dtype.
// ---------------------------------------------------------------------------
__global__ void detect_zero_kernel(const unsigned int* __restrict__ esrc_w,
                                   int n_edges, int n_nodes) {
    int i = blockIdx.x * 1024 + threadIdx.x;
    if (i < n_nodes) g_cnt[i] = 0;
    if (blockIdx.x == 0) {
        if (threadIdx.x < 128) g_bsum[threadIdx.x] = 0;
        __shared__ int s_ok;
        if (threadIdx.x == 0) s_ok = 1;
        __syncthreads();
        int n_check = n_edges < 1024 ? n_edges : 1024;
        if (threadIdx.x < n_check && esrc_w[2 * threadIdx.x + 1] != 0u)
            atomicAnd(&s_ok, 0);
        __syncthreads();
        if (threadIdx.x == 0) g_idx64 = s_ok;
    }
}

__device__ __forceinline__ int load_idx(const void* p, int e, int n_nodes) {
    int v;
    if (g_idx64) v = (int)((const long long*)p)[e];
    else         v = ((const int*)p)[e];
    if (v < 0) v = 0;
    if (v >= n_nodes) v = n_nodes - 1;
    return v;
}

// ---------------------------------------------------------------------------
__global__ void hist_kernel(const void* __restrict__ edge_dst,
                            int n_edges, int n_nodes) {
    int e0 = (blockIdx.x * blockDim.x + threadIdx.x) * 2;
    if (e0 >= n_edges) return;
    int d0 = load_idx(edge_dst, e0, n_nodes);
    asm volatile("red.global.add.u32 [%0], %1;"
                 :: "l"(&g_cnt[d0]), "r"(1) : "memory");
    if (e0 + 1 < n_edges) {
        int d1 = load_idx(edge_dst, e0 + 1, n_nodes);
        asm volatile("red.global.add.u32 [%0], %1;"
                     :: "l"(&g_cnt[d1]), "r"(1) : "memory");
    }
}

// ---------------------------------------------------------------------------
__device__ __forceinline__ int warp_incl_scan(int x, int lane) {
    #pragma unroll
    for (int off = 1; off < 32; off <<= 1) {
        int t = __shfl_up_sync(0xffffffffu, x, off);
        if (lane >= off) x += t;
    }
    return x;
}

// Single-kernel scan: local block scan + aggregate-only decoupled lookback.
// Grid <= 128 blocks (all resident on 148 SMs -> spin is safe).
// Flag packed in the same word as the value -> single-word atomicity, no fence.
__global__ void scan_kernel(int n) {
    __shared__ int wsum[32];
    __shared__ int s_pref;
    int b = blockIdx.x;
    int gid = b * 1024 + threadIdx.x;
    int lane = threadIdx.x & 31;
    int wid = threadIdx.x >> 5;

    int v = (gid < n) ? g_cnt[gid] : 0;
    int x = warp_incl_scan(v, lane);
    if (lane == 31) wsum[wid] = x;
    __syncthreads();
    if (wid == 0) wsum[lane] = warp_incl_scan(wsum[lane], lane);
    __syncthreads();
    int incl = x + (wid > 0 ? wsum[wid - 1] : 0);   // inclusive within block
    __syncthreads();                                 // wsum reuse below

    // publish this block's aggregate (value | flag, one word)
    if (threadIdx.x == 1023)
        *(volatile int*)&g_bsum[b] = incl | SCAN_FLAG;

    // lookback: lanes 0..127 read predecessors' aggregates
    if (threadIdx.x < 128) {
        int t = threadIdx.x;
        int p = 0;
        if (t < b) {
            volatile int* src = &g_bsum[t];
            int u;
            do { u = *src; } while (!(u & SCAN_FLAG));
            p = u & ~SCAN_FLAG;
        }
        #pragma unroll
        for (int off = 16; off > 0; off >>= 1)
            p += __shfl_xor_sync(0xffffffffu, p, off);
        if (lane == 0) wsum[wid] = p;
    }
    __syncthreads();
    if (threadIdx.x == 0)
        s_pref = wsum[0] + wsum[1] + wsum[2] + wsum[3];
    __syncthreads();

    if (gid < n) {
        int o = incl - v + s_pref;
        g_start[gid] = o;
        g_pos[gid] = o;
    }
}

// ---------------------------------------------------------------------------
__global__ void scatter_kernel(const void* __restrict__ edge_src,
                               const void* __restrict__ edge_dst,
                               int n_edges, int n_nodes) {
    int e = blockIdx.x * blockDim.x + threadIdx.x;
    if (e >= n_edges) return;
    int s = load_idx(edge_src, e, n_nodes);
    int d = load_idx(edge_dst, e, n_nodes);
    int pos = atomicAdd(&g_pos[d], 1);
    g_srcsorted[pos] = s;
}

// ---------------------------------------------------------------------------
// Fused SDDMM + SpMM gather: 16-lane group per dst node (2 nodes per warp).
// ---------------------------------------------------------------------------
__global__ __launch_bounds__(256) void spmm_gather_kernel(
        const float* __restrict__ feat, int n_nodes) {
    int g = (blockIdx.x * blockDim.x + threadIdx.x) >> 4;
    int lane = threadIdx.x & 15;
    unsigned hm = 0xFFFFu << (threadIdx.x & 16);
    if (g >= n_nodes) return;

    int start = g_start[g];
    int end = start + g_cnt[g];

    const float4 hd = *reinterpret_cast<const float4*>(feat + (size_t)g * D + lane * 4);
    float4 acc = make_float4(0.f, 0.f, 0.f, 0.f);

    int i = start;
    for (; i + 1 < end; i += 2) {
        int s0 = g_srcsorted[i];
        int s1 = g_srcsorted[i + 1];
        const float4 h0 = *reinterpret_cast<const float4*>(feat + (size_t)s0 * D + lane * 4);
        const float4 h1 = *reinterpret_cast<const float4*>(feat + (size_t)s1 * D + lane * 4);
        float p0 = h0.x * hd.x + h0.y * hd.y + h0.z * hd.z + h0.w * hd.w;
        float p1 = h1.x * hd.x + h1.y * hd.y + h1.z * hd.z + h1.w * hd.w;
        p0 += __shfl_xor_sync(hm, p0, 8);
        p1 += __shfl_xor_sync(hm, p1, 8);
        p0 += __shfl_xor_sync(hm, p0, 4);
        p1 += __shfl_xor_sync(hm, p1, 4);
        p0 += __shfl_xor_sync(hm, p0, 2);
        p1 += __shfl_xor_sync(hm, p1, 2);
        p0 += __shfl_xor_sync(hm, p0, 1);
        p1 += __shfl_xor_sync(hm, p1, 1);
        acc.x += h0.x * p0 + h1.x * p1;
        acc.y += h0.y * p0 + h1.y * p1;
        acc.z += h0.z * p0 + h1.z * p1;
        acc.w += h0.w * p0 + h1.w * p1;
    }
    if (i < end) {
        int s0 = g_srcsorted[i];
        const float4 h0 = *reinterpret_cast<const float4*>(feat + (size_t)s0 * D + lane * 4);
        float p0 = h0.x * hd.x + h0.y * hd.y + h0.z * hd.z + h0.w * hd.w;
        p0 += __shfl_xor_sync(hm, p0, 8);
        p0 += __shfl_xor_sync(hm, p0, 4);
        p0 += __shfl_xor_sync(hm, p0, 2);
        p0 += __shfl_xor_sync(hm, p0, 1);
        acc.x += h0.x * p0;
        acc.y += h0.y * p0;
        acc.z += h0.z * p0;
        acc.w += h0.w * p0;
    }

    *reinterpret_cast<float4*>(g_neigh + (size_t)g * D + lane * 4) = acc;
}

// ---------------------------------------------------------------------------
// GEMM: out = neigh @ W.T with FFMA2; sN stored PRE-DUPLICATED as f32x2
// pairs so no MOV-dups in the inner loop (12 LDS.128 + 32 FFMA2 per k4).
// ---------------------------------------------------------------------------
__global__ __launch_bounds__(256) void gemm_kernel(const float* __restrict__ W,
                                                   float* __restrict__ out,
                                                   int n_rows) {
    __shared__ float sWt[D][SPAD];    // [k][o]   17 KB
    __shared__ u64   sNd[GR][SNDS];   // [row][k] dup'd {v,v}  33 KB

    int tid = threadIdx.x;
    int tx = tid & 15;
    int ty = tid >> 4;

    #pragma unroll
    for (int it = 0; it < 16; it++) {
        int idx = tid + 256 * it;
        int o = idx >> 6;
        int k = idx & 63;
        sWt[k][o] = W[idx];
    }

    int row0 = blockIdx.x * GR;
    #pragma unroll
    for (int it = 0; it < 4; it++) {
        int idx = tid + 256 * it;
        int r = idx >> 4;
        int c4 = idx & 15;
        int row = row0 + r;
        float4 v = make_float4(0.f, 0.f, 0.f, 0.f);
        if (row < n_rows)
            v = *reinterpret_cast<const float4*>(g_neigh + (size_t)row * D + c4 * 4);
        u64 d0, d1, d2, d3;
        DUP_F32X2(d0, v.x); DUP_F32X2(d1, v.y);
        DUP_F32X2(d2, v.z); DUP_F32X2(d3, v.w);
        sNd[r][c4 * 4 + 0] = d0;
        sNd[r][c4 * 4 + 1] = d1;
        sNd[r][c4 * 4 + 2] = d2;
        sNd[r][c4 * 4 + 3] = d3;
    }
    __syncthreads();

    u64 accA[4], accB[4];
    #pragma unroll
    for (int j = 0; j < 4; j++) { accA[j] = 0ull; accB[j] = 0ull; }

    int c = tx * 4;
    #pragma unroll
    for (int k4 = 0; k4 < D / 4; k4++) {
        int k = k4 * 4;
        const ulonglong2 l0 = *reinterpret_cast<const ulonglong2*>(&sWt[k + 0][c]);
        const ulonglong2 l1 = *reinterpret_cast<const ulonglong2*>(&sWt[k + 1][c]);
        const ulonglong2 l2 = *reinterpret_cast<const ulonglong2*>(&sWt[k + 2][c]);
        const ulonglong2 l3 = *reinterpret_cast<const ulonglong2*>(&sWt[k + 3][c]);
        #pragma unroll
        for (int j = 0; j < 4; j++) {
            int row = ty + 16 * j;
            const ulonglong2 n01 = *reinterpret_cast<const ulonglong2*>(&sNd[row][k]);
            const ulonglong2 n23 = *reinterpret_cast<const ulonglong2*>(&sNd[row][k + 2]);
            FMA_F32X2(accA[j], n01.x, l0.x, accA[j]);
            FMA_F32X2(accB[j], n01.x, l0.y, accB[j]);
            FMA_F32X2(accA[j], n01.y, l1.x, accA[j]);
            FMA_F32X2(accB[j], n01.y, l1.y, accB[j]);
            FMA_F32X2(accA[j], n23.x, l2.x, accA[j]);
            FMA_F32X2(accB[j], n23.x, l2.y, accB[j]);
            FMA_F32X2(accA[j], n23.y, l3.x, accA[j]);
            FMA_F32X2(accB[j], n23.y, l3.y, accB[j]);
        }
    }

    #pragma unroll
    for (int j = 0; j < 4; j++) {
        int row = row0 + ty + 16 * j;
        if (row < n_rows) {
            ulonglong2 o;
            o.x = accA[j];
            o.y = accB[j];
            *reinterpret_cast<ulonglong2*>(out + (size_t)row * D + c) = o;
        }
    }
}

// ---------------------------------------------------------------------------
extern "C" void kernel_launch(void* const* d_in, const int* in_sizes, int n_in,
                              void* d_out, int out_size) {
    const float* feat = (const float*)d_in[0];
    const void*  esrc = d_in[1];
    const void*  edst = d_in[2];
    const float* W    = (const float*)d_in[3];
    float*       out  = (float*)d_out;

    int n_nodes = in_sizes[0] / D;
    int n_edges = in_sizes[1];

    int nblk = (n_nodes + 1023) / 1024;       // <= 128 (lookback residency)

    detect_zero_kernel<<<nblk, 1024>>>((const unsigned int*)esrc, n_edges, n_nodes);
    hist_kernel<<<(n_edges / 2 + 512) / 512, 512>>>(edst, n_edges, n_nodes);
    scan_kernel<<<nblk, 1024>>>(n_nodes);
    scatter_kernel<<<(n_edges + 511) / 512, 512>>>(esrc, edst, n_edges, n_nodes);
    spmm_gather_kernel<<<(n_nodes * 16 + 255) / 256, 256>>>(feat, n_nodes);
    gemm_kernel<<<(n_nodes + GR - 1) / GR, 256>>>(W, out, n_nodes);
}

// round 8
// speedup vs baseline: 1.0532x; 1.0532x over previous
#include <cuda_runtime.h>
#include <cstdint>

#define D 64
#define MAX_NODES 100000
#define MAX_EDGES 1600000
#define GR 64          // rows per GEMM block
#define SPAD 68        // smem row stride (floats)

typedef unsigned long long u64;

__device__ float g_neigh[MAX_NODES * D];
__device__ int   g_idx64;
__device__ int   g_cnt[MAX_NODES];
__device__ int   g_start[MAX_NODES];
__device__ int   g_pos[MAX_NODES];
__device__ int   g_srcsorted[MAX_EDGES];
__device__ int   g_bsum[128];

#define FMA_F32X2(d, a, b, c) \
    asm("fma.rn.f32x2 %0, %1, %2, %3;" : "=l"(d) : "l"(a), "l"(b), "l"(c))
#define DUP_F32X2(d, v) \
    asm("mov.b64 %0, {%1, %1};" : "=l"(d) : "f"(v))

// ---------------------------------------------------------------------------
// Fused: zero g_cnt + detect index dtype (block 0).
// ---------------------------------------------------------------------------
__global__ void detect_zero_kernel(const unsigned int* __restrict__ esrc_w,
                                   int n_edges, int n_nodes) {
    int i = blockIdx.x * 1024 + threadIdx.x;
    if (i < n_nodes) g_cnt[i] = 0;
    if (blockIdx.x == 0) {
        __shared__ int s_ok;
        if (threadIdx.x == 0) s_ok = 1;
        __syncthreads();
        int n_check = n_edges < 1024 ? n_edges : 1024;
        if (threadIdx.x < n_check && esrc_w[2 * threadIdx.x + 1] != 0u)
            atomicAnd(&s_ok, 0);
        __syncthreads();
        if (threadIdx.x == 0) g_idx64 = s_ok;
    }
}

__device__ __forceinline__ int clampi(int v, int n) {
    if (v < 0) v = 0;
    if (v >= n) v = n - 1;
    return v;
}

__device__ __forceinline__ int load_idx(const void* p, int e, int n_nodes) {
    int v;
    if (g_idx64) v = (int)((const long long*)p)[e];
    else         v = ((const int*)p)[e];
    return clampi(v, n_nodes);
}

// Load 4 consecutive indices (e0 = q*4, q*4+3 < n_edges) with vector loads.
__device__ __forceinline__ void load_idx4(const void* p, int q, int n_nodes,
                                          int* out) {
    if (!g_idx64) {
        int4 v = ((const int4*)p)[q];
        out[0] = clampi(v.x, n_nodes); out[1] = clampi(v.y, n_nodes);
        out[2] = clampi(v.z, n_nodes); out[3] = clampi(v.w, n_nodes);
    } else {
        longlong2 a = ((const longlong2*)p)[q * 2];
        longlong2 b = ((const longlong2*)p)[q * 2 + 1];
        out[0] = clampi((int)a.x, n_nodes); out[1] = clampi((int)a.y, n_nodes);
        out[2] = clampi((int)b.x, n_nodes); out[3] = clampi((int)b.y, n_nodes);
    }
}

// ---------------------------------------------------------------------------
// Histogram: 4 edges/thread, REDG (no return).
// ---------------------------------------------------------------------------
__global__ void hist_kernel(const void* __restrict__ edge_dst,
                            int n_edges, int n_nodes) {
    int q = blockIdx.x * blockDim.x + threadIdx.x;
    int e0 = q * 4;
    if (e0 >= n_edges) return;
    if (e0 + 3 < n_edges) {
        int d[4];
        load_idx4(edge_dst, q, n_nodes, d);
        #pragma unroll
        for (int j = 0; j < 4; j++)
            asm volatile("red.global.add.u32 [%0], %1;"
                         :: "l"(&g_cnt[d[j]]), "r"(1) : "memory");
    } else {
        for (int e = e0; e < n_edges; e++) {
            int dd = load_idx(edge_dst, e, n_nodes);
            asm volatile("red.global.add.u32 [%0], %1;"
                         :: "l"(&g_cnt[dd]), "r"(1) : "memory");
        }
    }
}

// ---------------------------------------------------------------------------
// Scan (R6 two-kernel version — known good).
// ---------------------------------------------------------------------------
__device__ __forceinline__ int warp_incl_scan(int x, int lane) {
    #pragma unroll
    for (int off = 1; off < 32; off <<= 1) {
        int t = __shfl_up_sync(0xffffffffu, x, off);
        if (lane >= off) x += t;
    }
    return x;
}

__global__ void scanA_kernel(int n) {
    __shared__ int wsum[32];
    int gid = blockIdx.x * 1024 + threadIdx.x;
    int lane = threadIdx.x & 31;
    int wid = threadIdx.x >> 5;
    int v = (gid < n) ? g_cnt[gid] : 0;
    int x = warp_incl_scan(v, lane);
    if (lane == 31) wsum[wid] = x;
    __syncthreads();
    if (wid == 0) wsum[lane] = warp_incl_scan(wsum[lane], lane);
    __syncthreads();
    int incl = x + (wid > 0 ? wsum[wid - 1] : 0);
    if (gid < n) g_start[gid] = incl - v;
    if (threadIdx.x == 1023) g_bsum[blockIdx.x] = incl;
}

__global__ void scan_fixup_kernel(int n) {
    __shared__ int warp_part[4];
    __shared__ int s_prefix;
    int t = threadIdx.x;
    if (t < 128) {
        int v = (t < blockIdx.x) ? g_bsum[t] : 0;
        #pragma unroll
        for (int off = 16; off > 0; off >>= 1)
            v += __shfl_xor_sync(0xffffffffu, v, off);
        if ((t & 31) == 0) warp_part[t >> 5] = v;
    }
    __syncthreads();
    if (t == 0) s_prefix = warp_part[0] + warp_part[1] + warp_part[2] + warp_part[3];
    __syncthreads();
    int gid = blockIdx.x * 1024 + t;
    if (gid < n) {
        int o = g_start[gid] + s_prefix;
        g_start[gid] = o;
        g_pos[gid] = o;
    }
}

// ---------------------------------------------------------------------------
// Scatter: 4 edges/thread, 4 independent atomics in flight (MLP=4).
// ---------------------------------------------------------------------------
__global__ void scatter_kernel(const void* __restrict__ edge_src,
                               const void* __restrict__ edge_dst,
                               int n_edges, int n_nodes) {
    int q = blockIdx.x * blockDim.x + threadIdx.x;
    int e0 = q * 4;
    if (e0 >= n_edges) return;
    if (e0 + 3 < n_edges) {
        int s[4], d[4], p[4];
        load_idx4(edge_src, q, n_nodes, s);
        load_idx4(edge_dst, q, n_nodes, d);
        #pragma unroll
        for (int j = 0; j < 4; j++)
            p[j] = atomicAdd(&g_pos[d[j]], 1);
        #pragma unroll
        for (int j = 0; j < 4; j++)
            g_srcsorted[p[j]] = s[j];
    } else {
        for (int e = e0; e < n_edges; e++) {
            int ss = load_idx(edge_src, e, n_nodes);
            int dd = load_idx(edge_dst, e, n_nodes);
            int pos = atomicAdd(&g_pos[dd], 1);
            g_srcsorted[pos] = ss;
        }
    }
}

// ---------------------------------------------------------------------------
// Fused SDDMM + SpMM gather: 16-lane group per dst node (2 nodes per warp).
// ---------------------------------------------------------------------------
__global__ __launch_bounds__(256) void spmm_gather_kernel(
        const float* __restrict__ feat, int n_nodes) {
    int g = (blockIdx.x * blockDim.x + threadIdx.x) >> 4;
    int lane = threadIdx.x & 15;
    unsigned hm = 0xFFFFu << (threadIdx.x & 16);
    if (g >= n_nodes) return;

    int start = g_start[g];
    int end = start + g_cnt[g];

    const float4 hd = *reinterpret_cast<const float4*>(feat + (size_t)g * D + lane * 4);
    float4 acc = make_float4(0.f, 0.f, 0.f, 0.f);

    int i = start;
    for (; i + 1 < end; i += 2) {
        int s0 = g_srcsorted[i];
        int s1 = g_srcsorted[i + 1];
        const float4 h0 = *reinterpret_cast<const float4*>(feat + (size_t)s0 * D + lane * 4);
        const float4 h1 = *reinterpret_cast<const float4*>(feat + (size_t)s1 * D + lane * 4);
        float p0 = h0.x * hd.x + h0.y * hd.y + h0.z * hd.z + h0.w * hd.w;
        float p1 = h1.x * hd.x + h1.y * hd.y + h1.z * hd.z + h1.w * hd.w;
        p0 += __shfl_xor_sync(hm, p0, 8);
        p1 += __shfl_xor_sync(hm, p1, 8);
        p0 += __shfl_xor_sync(hm, p0, 4);
        p1 += __shfl_xor_sync(hm, p1, 4);
        p0 += __shfl_xor_sync(hm, p0, 2);
        p1 += __shfl_xor_sync(hm, p1, 2);
        p0 += __shfl_xor_sync(hm, p0, 1);
        p1 += __shfl_xor_sync(hm, p1, 1);
        acc.x += h0.x * p0 + h1.x * p1;
        acc.y += h0.y * p0 + h1.y * p1;
        acc.z += h0.z * p0 + h1.z * p1;
        acc.w += h0.w * p0 + h1.w * p1;
    }
    if (i < end) {
        int s0 = g_srcsorted[i];
        const float4 h0 = *reinterpret_cast<const float4*>(feat + (size_t)s0 * D + lane * 4);
        float p0 = h0.x * hd.x + h0.y * hd.y + h0.z * hd.z + h0.w * hd.w;
        p0 += __shfl_xor_sync(hm, p0, 8);
        p0 += __shfl_xor_sync(hm, p0, 4);
        p0 += __shfl_xor_sync(hm, p0, 2);
        p0 += __shfl_xor_sync(hm, p0, 1);
        acc.x += h0.x * p0;
        acc.y += h0.y * p0;
        acc.z += h0.z * p0;
        acc.w += h0.w * p0;
    }

    *reinterpret_cast<float4*>(g_neigh + (size_t)g * D + lane * 4) = acc;
}

// ---------------------------------------------------------------------------
// GEMM: out = neigh @ W.T (R6 version — FFMA2 with in-loop dups; 113.2 base).
// ---------------------------------------------------------------------------
__global__ __launch_bounds__(256) void gemm_kernel(const float* __restrict__ W,
                                                   float* __restrict__ out,
                                                   int n_rows) {
    __shared__ float sWt[D][SPAD];
    __shared__ float sN[GR][SPAD];

    int tid = threadIdx.x;
    int tx = tid & 15;
    int ty = tid >> 4;

    #pragma unroll
    for (int it = 0; it < 16; it++) {
        int idx = tid + 256 * it;
        int o = idx >> 6;
        int k = idx & 63;
        sWt[k][o] = W[idx];
    }

    int row0 = blockIdx.x * GR;
    #pragma unroll
    for (int it = 0; it < 4; it++) {
        int idx = tid + 256 * it;
        int r = idx >> 4;
        int c4 = idx & 15;
        int row = row0 + r;
        float4 v = make_float4(0.f, 0.f, 0.f, 0.f);
        if (row < n_rows)
            v = *reinterpret_cast<const float4*>(g_neigh + (size_t)row * D + c4 * 4);
        *reinterpret_cast<float4*>(&sN[r][c4 * 4]) = v;
    }
    __syncthreads();

    u64 accA[4], accB[4];
    #pragma unroll
    for (int j = 0; j < 4; j++) { accA[j] = 0ull; accB[j] = 0ull; }

    int c = tx * 4;
    #pragma unroll
    for (int k4 = 0; k4 < D / 4; k4++) {
        int k = k4 * 4;
        const ulonglong2 l0 = *reinterpret_cast<const ulonglong2*>(&sWt[k + 0][c]);
        const ulonglong2 l1 = *reinterpret_cast<const ulonglong2*>(&sWt[k + 1][c]);
        const ulonglong2 l2 = *reinterpret_cast<const ulonglong2*>(&sWt[k + 2][c]);
        const ulonglong2 l3 = *reinterpret_cast<const ulonglong2*>(&sWt[k + 3][c]);
        #pragma unroll
        for (int j = 0; j < 4; j++) {
            const float4 nb = *reinterpret_cast<const float4*>(&sN[ty + 16 * j][k]);
            u64 dx, dy, dz, dw;
            DUP_F32X2(dx, nb.x);
            DUP_F32X2(dy, nb.y);
            DUP_F32X2(dz, nb.z);
            DUP_F32X2(dw, nb.w);
            FMA_F32X2(accA[j], dx, l0.x, accA[j]);
            FMA_F32X2(accB[j], dx, l0.y, accB[j]);
            FMA_F32X2(accA[j], dy, l1.x, accA[j]);
            FMA_F32X2(accB[j], dy, l1.y, accB[j]);
            FMA_F32X2(accA[j], dz, l2.x, accA[j]);
            FMA_F32X2(accB[j], dz, l2.y, accB[j]);
            FMA_F32X2(accA[j], dw, l3.x, accA[j]);
            FMA_F32X2(accB[j], dw, l3.y, accB[j]);
        }
    }

    #pragma unroll
    for (int j = 0; j < 4; j++) {
        int row = row0 + ty + 16 * j;
        if (row < n_rows) {
            ulonglong2 o;
            o.x = accA[j];
            o.y = accB[j];
            *reinterpret_cast<ulonglong2*>(out + (size_t)row * D + c) = o;
        }
    }
}

// ---------------------------------------------------------------------------
extern "C" void kernel_launch(void* const* d_in, const int* in_sizes, int n_in,
                              void* d_out, int out_size) {
    const float* feat = (const float*)d_in[0];
    const void*  esrc = d_in[1];
    const void*  edst = d_in[2];
    const float* W    = (const float*)d_in[3];
    float*       out  = (float*)d_out;

    int n_nodes = in_sizes[0] / D;
    int n_edges = in_sizes[1];

    int nblk = (n_nodes + 1023) / 1024;       // <= 128
    int nquad = (n_edges + 3) / 4;

    detect_zero_kernel<<<nblk, 1024>>>((const unsigned int*)esrc, n_edges, n_nodes);
    hist_kernel<<<(nquad + 511) / 512, 512>>>(edst, n_edges, n_nodes);
    scanA_kernel<<<nblk, 1024>>>(n_nodes);
    scan_fixup_kernel<<<nblk, 1024>>>(n_nodes);
    scatter_kernel<<<(nquad + 511) / 512, 512>>>(esrc, edst, n_edges, n_nodes);
    spmm_gather_kernel<<<(n_nodes * 16 + 255) / 256, 256>>>(feat, n_nodes);
    gemm_kernel<<<(n_nodes + GR - 1) / GR, 256>>>(W, out, n_nodes);
}